// round 1
// baseline (speedup 1.0000x reference)
#include <cuda_runtime.h>
#include <cstdint>

// Flag: 1 if index tensor is int64, 0 if int32. Set each launch by a probe
// kernel (deterministic — depends only on input data), read by the main kernel.
__device__ int g_idx_is_64;

// Probe: if x is int64, the high word of every entry is 0 (indices < 128000).
// If x is int32, the "high words" are actually other random indices in
// [0, 128000); probability all 64 checked words are 0 is ~(1/128000)^64 ~ 0.
__global__ void detect_idx_dtype_kernel(const int* __restrict__ x32, int n_tokens) {
    if (threadIdx.x == 0 && blockIdx.x == 0) {
        int checks = n_tokens < 64 ? n_tokens : 64;
        int is64 = 1;
        for (int i = 0; i < checks; ++i) {
            if (x32[2 * i + 1] != 0) { is64 = 0; break; }
        }
        g_idx_is_64 = is64;
    }
}

// One CTA per token. 256 threads; thread t handles elements [4t, 4t+4) of the
// 1024-wide row: one 16B weight load, dequant, one 16B streaming store.
__global__ __launch_bounds__(256, 8)
void int4_embedding_kernel(const void* __restrict__ x_raw,
                           const int4* __restrict__ weight,   // [V, 256] int4 vecs
                           const float* __restrict__ scale,   // [V, 32]
                           const int* __restrict__ zero_point,// [V, 32]
                           float4* __restrict__ out)          // [T, 256]
{
    const int token = blockIdx.x;
    const int t = threadIdx.x;          // 0..255

    long long v;
    if (g_idx_is_64) {
        v = __ldg(((const long long*)x_raw) + token);
    } else {
        v = (long long)__ldg(((const int*)x_raw) + token);
    }

    const int g = t >> 3;               // element group = (4t)/32
    const size_t srow = (size_t)v * 32 + g;
    const float s = __ldg(scale + srow);
    const float z = (float)__ldg(zero_point + srow);

    const int4 w = __ldg(weight + (size_t)v * 256 + t);

    float4 o;
    o.x = ((float)w.x - z) * s;
    o.y = ((float)w.y - z) * s;
    o.z = ((float)w.z - z) * s;
    o.w = ((float)w.w - z) * s;

    // Streaming store: output is write-once, never re-read — keep it out of L2
    // so L2 capacity goes to weight-row reuse (duplicate indices).
    __stcs(out + (size_t)token * 256 + t, o);
}

extern "C" void kernel_launch(void* const* d_in, const int* in_sizes, int n_in,
                              void* d_out, int out_size) {
    const void*  x      = d_in[0];                    // [32, 2048] int64 (or int32)
    const int4*  weight = (const int4*)d_in[1];       // [128000, 1024] int32
    const float* scale  = (const float*)d_in[2];      // [128000, 32] fp32
    const int*   zp     = (const int*)d_in[3];        // [128000, 32] int32
    float4*      out    = (float4*)d_out;             // [32, 2048, 1024] fp32

    const int n_tokens = in_sizes[0];                 // 65536

    detect_idx_dtype_kernel<<<1, 32>>>((const int*)x, n_tokens);
    int4_embedding_kernel<<<n_tokens, 256>>>(x, weight, scale, zp, out);
}

// round 2
// speedup vs baseline: 1.2554x; 1.2554x over previous
#include <cuda_runtime.h>
#include <cstdint>

// Flag: 1 if index tensor is int64, 0 if int32. Set each launch by a probe
// kernel (deterministic — depends only on input data), read by the main kernel.
__device__ int g_idx_is_64;

// Parallel probe: if x is int64, the high 32-bit word of every entry is 0
// (indices < 128000 << 2^31). If x is int32, those words are other random
// indices in [0, 128000); P(all 32 sampled words are 0) ≈ (1/128000)^32 ≈ 0.
// One warp, one load per lane, one ballot — single memory round-trip.
__global__ void detect_idx_dtype_kernel(const int* __restrict__ x32, int n_tokens) {
    const int lane = threadIdx.x;            // 32 threads
    int nonzero = 0;
    if (lane < n_tokens) {
        nonzero = (__ldg(x32 + 2 * lane + 1) != 0);
    }
    const unsigned mask = __ballot_sync(0xFFFFFFFFu, nonzero);
    if (lane == 0) g_idx_is_64 = (mask == 0u);
}

#define TPC 4   // tokens per CTA -> per-thread MLP of 4 on the weight loads

// One CTA per TPC tokens, 256 threads. Thread t owns 16-byte vector t of each
// token's 1024-element row: TPC independent 16B weight loads in flight, then
// scale/zp, then dequant + TPC streaming 16B stores.
__global__ __launch_bounds__(256, 6)
void int4_embedding_kernel(const void* __restrict__ x_raw,
                           const int4* __restrict__ weight,    // [V, 256] int4 vecs
                           const float* __restrict__ scale,    // [V, 32]
                           const int* __restrict__ zero_point, // [V, 32]
                           float4* __restrict__ out,           // [T, 256]
                           int n_tokens)
{
    const int t = threadIdx.x;                          // 0..255
    const long long base = (long long)blockIdx.x * TPC;
    const int nt = (int)(n_tokens - base) < TPC ? (int)(n_tokens - base) : TPC;

    long long v[TPC];
    if (g_idx_is_64) {
        const long long* x = (const long long*)x_raw;
        #pragma unroll
        for (int i = 0; i < TPC; ++i)
            v[i] = (i < nt) ? __ldg(x + base + i) : 0;
    } else {
        const int* x = (const int*)x_raw;
        #pragma unroll
        for (int i = 0; i < TPC; ++i)
            v[i] = (i < nt) ? (long long)__ldg(x + base + i) : 0;
    }

    // Issue all TPC weight loads back-to-back (independent addresses -> MLP=TPC)
    int4 w[TPC];
    #pragma unroll
    for (int i = 0; i < TPC; ++i)
        w[i] = __ldg(weight + (size_t)v[i] * 256 + t);

    const int g = t >> 3;                                // group = (4t)/32
    float s[TPC], z[TPC];
    #pragma unroll
    for (int i = 0; i < TPC; ++i) {
        const size_t srow = (size_t)v[i] * 32 + g;
        s[i] = __ldg(scale + srow);
        z[i] = (float)__ldg(zero_point + srow);
    }

    #pragma unroll
    for (int i = 0; i < TPC; ++i) {
        float4 o;
        o.x = ((float)w[i].x - z[i]) * s[i];
        o.y = ((float)w[i].y - z[i]) * s[i];
        o.z = ((float)w[i].z - z[i]) * s[i];
        o.w = ((float)w[i].w - z[i]) * s[i];
        if (i < nt) {
            // Streaming store: output is write-once — keep it out of L2 so L2
            // capacity goes to weight-row reuse (duplicate indices).
            __stcs(out + (size_t)(base + i) * 256 + t, o);
        }
    }
}

extern "C" void kernel_launch(void* const* d_in, const int* in_sizes, int n_in,
                              void* d_out, int out_size) {
    const void*  x      = d_in[0];                    // [32, 2048] int64 (or int32)
    const int4*  weight = (const int4*)d_in[1];       // [128000, 1024] int32
    const float* scale  = (const float*)d_in[2];      // [128000, 32] fp32
    const int*   zp     = (const int*)d_in[3];        // [128000, 32] int32
    float4*      out    = (float4*)d_out;             // [32, 2048, 1024] fp32

    const int n_tokens = in_sizes[0];                 // 65536

    detect_idx_dtype_kernel<<<1, 32>>>((const int*)x, n_tokens);

    const int grid = (n_tokens + TPC - 1) / TPC;
    int4_embedding_kernel<<<grid, 256>>>(x, weight, scale, zp, out, n_tokens);
}

// round 4
// speedup vs baseline: 1.2819x; 1.0211x over previous
#include <cuda_runtime.h>
#include <cstdint>

#define TPC 4   // tokens per CTA -> per-thread MLP of 4 on the weight loads

// One CTA per TPC tokens, 256 threads. Thread t owns 16-byte vector t of each
// token's 1024-element row.
//
// Index dtype (int64 vs int32) is detected inline, per CTA, with no extra
// memory round-trip: lane L probes the high 32-bit word of entry L of x
// (assuming int64 layout; same 256B region for every CTA -> L2/L1 hot). If x
// is int64, every high word is 0 (indices < 128000); if int32, those words
// are random indices in [0,128000) and P(all 32 == 0) ~ (1/128000)^32 ~ 0.
// Both index interpretations are loaded speculatively in the same batch, then
// selected after one ballot — weight loads start after a single round-trip.
__global__ __launch_bounds__(256, 6)
void int4_embedding_kernel(const int* __restrict__ x32,
                           const int4* __restrict__ weight,    // [V, 256] int4 vecs
                           const float* __restrict__ scale,    // [V, 32]
                           const int* __restrict__ zero_point, // [V, 32]
                           float4* __restrict__ out,           // [T, 256]
                           int n_tokens)
{
    const int t = threadIdx.x;                          // 0..255
    const int lane = t & 31;
    const long long base = (long long)blockIdx.x * TPC;
    const int rem = (int)(n_tokens - base);
    const int nt = rem < TPC ? rem : TPC;

    // --- all independent loads issued together ---------------------------
    // probe: high word of entry `lane` (assuming int64 layout)
    const int hi_probe = (lane < n_tokens) ? __ldg(x32 + 2 * lane + 1) : 0;

    // speculative index loads under both interpretations
    int lo64[TPC], lo32[TPC];
    #pragma unroll
    for (int i = 0; i < TPC; ++i) {
        lo64[i] = (i < nt) ? __ldg(x32 + 2 * (base + i)) : 0;  // int64 low word
        lo32[i] = (i < nt) ? __ldg(x32 + (base + i))     : 0;  // int32 value
    }

    // --- resolve dtype (one ballot, no extra round-trip) ------------------
    const bool is64 = (__ballot_sync(0xFFFFFFFFu, hi_probe != 0) == 0u);

    long long v[TPC];
    #pragma unroll
    for (int i = 0; i < TPC; ++i)
        v[i] = (long long)(is64 ? lo64[i] : lo32[i]);

    // --- weight loads: TPC independent 16B loads in flight (MLP=TPC) ------
    int4 w[TPC];
    #pragma unroll
    for (int i = 0; i < TPC; ++i)
        w[i] = __ldg(weight + (size_t)v[i] * 256 + t);

    const int g = t >> 3;                                // group = (4t)/32
    float s[TPC], z[TPC];
    #pragma unroll
    for (int i = 0; i < TPC; ++i) {
        const size_t srow = (size_t)v[i] * 32 + g;
        s[i] = __ldg(scale + srow);
        z[i] = (float)__ldg(zero_point + srow);
    }

    #pragma unroll
    for (int i = 0; i < TPC; ++i) {
        float4 o;
        o.x = ((float)w[i].x - z[i]) * s[i];
        o.y = ((float)w[i].y - z[i]) * s[i];
        o.z = ((float)w[i].z - z[i]) * s[i];
        o.w = ((float)w[i].w - z[i]) * s[i];
        if (i < nt) {
            // Streaming store: output is write-once — keep it out of L2 so L2
            // capacity goes to weight-row reuse (duplicate indices).
            __stcs(out + (size_t)(base + i) * 256 + t, o);
        }
    }
}

extern "C" void kernel_launch(void* const* d_in, const int* in_sizes, int n_in,
                              void* d_out, int out_size) {
    const int*   x      = (const int*)d_in[0];        // [32, 2048] int64 (or int32)
    const int4*  weight = (const int4*)d_in[1];       // [128000, 1024] int32
    const float* scale  = (const float*)d_in[2];      // [128000, 32] fp32
    const int*   zp     = (const int*)d_in[3];        // [128000, 32] int32
    float4*      out    = (float4*)d_out;             // [32, 2048, 1024] fp32

    const int n_tokens = in_sizes[0];                 // 65536

    const int grid = (n_tokens + TPC - 1) / TPC;
    int4_embedding_kernel<<<grid, 256>>>(x, weight, scale, zp, out, n_tokens);
}